// round 11
// baseline (speedup 1.0000x reference)
#include <cuda_runtime.h>

#define HH 256
#define WW 256
#define NT 16
#define NB 8
#define NIMG (NB*NT)
#define HW (HH*WW)
#define SAMPLE_ELEMS (NT*HW)          // 1048576
#define WIN 11
#define PADW 5
#define SPLIT 2
#define SEG (HH/SPLIT)                // 128
#define NLOADS (SEG + 10)             // 138 row loads per segment
#define BW 128                        // columns per block
#define RED_BLKS 64
#define GRID1 (NB*RED_BLKS)           // 512
#define GRID2 (NIMG*SPLIT*2)          // 512 (frames x segs x col-halves)
#define SSIM_EPS 1e-6f
#define C1_ (1.0e-4f)
#define C2_ (9.0e-4f)
#define C3_ (4.5e-4f)

// canonical 11-tap sigma=1.5 gaussian
#define GW0 0.0010283799f
#define GW1 0.0075987583f
#define GW2 0.0360007723f
#define GW3 0.1093606947f
#define GW4 0.2130055329f
#define GW5 0.2660117190f

typedef unsigned long long u64;

// scratch (no allocations allowed)
__device__ float g_partial[5 * GRID1];   // stat-major: pmn,pmx,tmn,tmx,tsum
__device__ float g_params[NB * 4];       // mnt, invt, mnp, invp
__device__ float g_valid[NB];
__device__ float g_ssim[NB];
__device__ unsigned int g_cnt1;
__device__ unsigned int g_cnt2;

// ---- packed f32x2 helpers -------------------------------------------------
__device__ __forceinline__ u64 pk2(float x, float y) {
    u64 r; asm("mov.b64 %0,{%1,%2};" : "=l"(r) : "f"(x), "f"(y)); return r;
}
__device__ __forceinline__ void upk2(float& x, float& y, u64 v) {
    asm("mov.b64 {%0,%1},%2;" : "=f"(x), "=f"(y) : "l"(v));
}
__device__ __forceinline__ u64 fma2(u64 a, u64 b, u64 c) {
    u64 d; asm("fma.rn.f32x2 %0,%1,%2,%3;" : "=l"(d) : "l"(a), "l"(b), "l"(c)); return d;
}
__device__ __forceinline__ u64 mul2(u64 a, u64 b) {
    u64 d; asm("mul.rn.f32x2 %0,%1,%2;" : "=l"(d) : "l"(a), "l"(b)); return d;
}

// ---------------------------------------------------------------------------
// Kernel 1: per-sample min/max of pred & tgt, sum of tgt (64 blocks/sample),
//           fused finalize in the last-arriving block.
// ---------------------------------------------------------------------------
__global__ __launch_bounds__(256) void reduce_kernel(const float* __restrict__ pred,
                                                     const float* __restrict__ tgt) {
    int b   = blockIdx.x >> 6;
    int blk = blockIdx.x & 63;
    int tid = threadIdx.x;

    const float4* p4 = (const float4*)(pred + (size_t)b * SAMPLE_ELEMS + (size_t)blk * 16384);
    const float4* t4 = (const float4*)(tgt  + (size_t)b * SAMPLE_ELEMS + (size_t)blk * 16384);

    float pmn = 1e30f, pmx = -1e30f, tmn = 1e30f, tmx = -1e30f, ts = 0.f;
    #pragma unroll 4
    for (int i = tid; i < 4096; i += 256) {
        float4 a = p4[i];
        pmn = fminf(pmn, fminf(fminf(a.x, a.y), fminf(a.z, a.w)));
        pmx = fmaxf(pmx, fmaxf(fmaxf(a.x, a.y), fmaxf(a.z, a.w)));
        float4 c = t4[i];
        tmn = fminf(tmn, fminf(fminf(c.x, c.y), fminf(c.z, c.w)));
        tmx = fmaxf(tmx, fmaxf(fmaxf(c.x, c.y), fmaxf(c.z, c.w)));
        ts += (c.x + c.y) + (c.z + c.w);
    }
    #pragma unroll
    for (int o = 16; o; o >>= 1) {
        pmn = fminf(pmn, __shfl_xor_sync(~0u, pmn, o));
        pmx = fmaxf(pmx, __shfl_xor_sync(~0u, pmx, o));
        tmn = fminf(tmn, __shfl_xor_sync(~0u, tmn, o));
        tmx = fmaxf(tmx, __shfl_xor_sync(~0u, tmx, o));
        ts += __shfl_xor_sync(~0u, ts, o);
    }
    __shared__ float sm[8 * 5];
    int wid = tid >> 5;
    if ((tid & 31) == 0) {
        sm[wid * 5 + 0] = pmn; sm[wid * 5 + 1] = pmx;
        sm[wid * 5 + 2] = tmn; sm[wid * 5 + 3] = tmx;
        sm[wid * 5 + 4] = ts;
    }
    __syncthreads();
    if (tid == 0) {
        float a0 = sm[0], a1 = sm[1], a2 = sm[2], a3 = sm[3], a4 = sm[4];
        #pragma unroll
        for (int w = 1; w < 8; ++w) {
            a0 = fminf(a0, sm[w * 5 + 0]);
            a1 = fmaxf(a1, sm[w * 5 + 1]);
            a2 = fminf(a2, sm[w * 5 + 2]);
            a3 = fmaxf(a3, sm[w * 5 + 3]);
            a4 += sm[w * 5 + 4];
        }
        int base = b * RED_BLKS + blk;
        g_partial[0 * GRID1 + base] = a0;
        g_partial[1 * GRID1 + base] = a1;
        g_partial[2 * GRID1 + base] = a2;
        g_partial[3 * GRID1 + base] = a3;
        g_partial[4 * GRID1 + base] = a4;
        __threadfence();
    }
    __syncthreads();

    __shared__ int amLast;
    if (tid == 0) amLast = (atomicAdd(&g_cnt1, 1u) == GRID1 - 1);
    __syncthreads();
    if (!amLast) return;

    int wb  = tid >> 5;   // warp wb -> sample wb
    int lid = tid & 31;
    {
        int i0 = wb * RED_BLKS + lid;
        int i1 = i0 + 32;
        float a = fminf(g_partial[0 * GRID1 + i0], g_partial[0 * GRID1 + i1]);
        float c = fmaxf(g_partial[1 * GRID1 + i0], g_partial[1 * GRID1 + i1]);
        float d = fminf(g_partial[2 * GRID1 + i0], g_partial[2 * GRID1 + i1]);
        float e = fmaxf(g_partial[3 * GRID1 + i0], g_partial[3 * GRID1 + i1]);
        float s =       g_partial[4 * GRID1 + i0] + g_partial[4 * GRID1 + i1];
        #pragma unroll
        for (int o = 16; o; o >>= 1) {
            a = fminf(a, __shfl_xor_sync(~0u, a, o));
            c = fmaxf(c, __shfl_xor_sync(~0u, c, o));
            d = fminf(d, __shfl_xor_sync(~0u, d, o));
            e = fmaxf(e, __shfl_xor_sync(~0u, e, o));
            s += __shfl_xor_sync(~0u, s, o);
        }
        if (lid == 0) {
            float invp = 1.0f / fmaxf(c - a, SSIM_EPS);
            float invt = 1.0f / fmaxf(e - d, SSIM_EPS);
            g_params[wb * 4 + 0] = d;
            g_params[wb * 4 + 1] = invt;
            g_params[wb * 4 + 2] = a;
            g_params[wb * 4 + 3] = invp;
            g_valid[wb] = (s != 0.0f) ? 1.0f : 0.0f;
            g_ssim[wb]  = 0.0f;
        }
    }
    if (tid == 0) g_cnt1 = 0;   // reset for next graph replay
}

// ---------------------------------------------------------------------------
// Kernel 2: fused normalize + separable conv + SSIM, field-packed f32x2.
// TWO rows per __syncthreads (4-slot rotating buffer): half the barriers,
// two independent h-conv chains between barriers. Register prefetch 2 rows
// ahead. Last block computes the final scalar loss.
// ---------------------------------------------------------------------------
__global__ __launch_bounds__(BW, 4) void conv_kernel(const float* __restrict__ pred,
                                                     const float* __restrict__ tgt,
                                                     float* __restrict__ out, int out_size) {
    const float w[WIN] = {GW0, GW1, GW2, GW3, GW4, GW5, GW4, GW3, GW2, GW1, GW0};

    int blk  = blockIdx.x;
    int half = blk & 1;               // column half
    int seg  = (blk >> 1) & 1;        // row segment
    int n    = blk >> 2;              // frame
    int b    = n >> 4;
    int tid  = threadIdx.x;
    int c0   = half * BW;

    float mnt  = g_params[b * 4 + 0];
    float invt = g_params[b * 4 + 1];
    float mnp  = g_params[b * 4 + 2];
    float invp = g_params[b * 4 + 3];
    float ctc = -mnt * invt;          // tn = fma(t, invt, ctc)
    float cpc = -mnp * invp;

    // 6 distinct packed weights (symmetric kernel)
    u64 w2[6];
    w2[0] = pk2(GW0, GW0); w2[1] = pk2(GW1, GW1); w2[2] = pk2(GW2, GW2);
    w2[3] = pk2(GW3, GW3); w2[4] = pk2(GW4, GW4); w2[5] = pk2(GW5, GW5);

    // 4-slot rotating row buffers: {t_norm, p_norm} per column,
    // positions 0..137 = global columns [c0-5, c0+132].
    __shared__ u64 sb[4][BW + 16];

    int r0 = seg * SEG;
    const float* tb = tgt  + (size_t)n * HW;
    const float* pb = pred + (size_t)n * HW;

    int gcol  = c0 - PADW + tid;            // position tid
    int gcol2 = gcol + BW;                  // position tid+BW (only tid<10)
    bool inc  = (gcol >= 0) && (gcol < WW);
    bool inc2 = (tid < 10) && (gcol2 < WW);

    u64 rmu[WIN], rsq[WIN];
    float rtp[WIN];
    float acc = 0.f;

    // row loader: zero outside image / outside NLOADS
    #define LOADROW(I, X0, X1) do {                                              \
        X0 = 0ull; X1 = 0ull;                                                    \
        int y_ = r0 - PADW + (I);                                                \
        if ((I) < NLOADS && y_ >= 0 && y_ < HH) {                                \
            if (inc)  { int id_ = y_ * WW + gcol;                                \
                X0 = pk2(fmaf(tb[id_], invt, ctc), fmaf(pb[id_], invp, cpc)); }  \
            if (inc2) { int id_ = y_ * WW + gcol2;                               \
                X1 = pk2(fmaf(tb[id_], invt, ctc), fmaf(pb[id_], invp, cpc)); }  \
        }                                                                        \
    } while (0)

    u64 cA0, cA1, cB0, cB1;
    LOADROW(0, cA0, cA1);
    LOADROW(1, cB0, cB1);

    #pragma unroll 1
    for (int base = 0; base < 154; base += 22) {
        #pragma unroll
        for (int j = 0; j < 11; ++j) {
            int i0 = base + 2 * j;            // even row
            int i1 = i0 + 1;                  // odd row
            int s0 = i0 & 3, s1 = i1 & 3;

            // store both prefetched rows, one barrier
            sb[s0][tid] = cA0;  if (tid < 10) sb[s0][BW + tid] = cA1;
            sb[s1][tid] = cB0;  if (tid < 10) sb[s1][BW + tid] = cB1;
            __syncthreads();

            // prefetch rows i0+2, i1+2 (full iteration of latency cover)
            LOADROW(i0 + 2, cA0, cA1);
            LOADROW(i1 + 2, cB0, cB1);

            // two independent horizontal convs (rows i0, i1)
            u64 mu0 = 0ull, sq0 = 0ull, mu1 = 0ull, sq1 = 0ull;
            float tp0 = 0.f, tp1 = 0.f;
            {
                const u64* rowA = &sb[s0][tid];
                const u64* rowB = &sb[s1][tid];
                #pragma unroll
                for (int k = 0; k < WIN; ++k) {
                    u64 wk = w2[k < 6 ? k : 10 - k];
                    u64 mA = rowA[k];
                    mu0 = fma2(wk, mA, mu0);
                    u64 wmA = mul2(wk, mA);
                    sq0 = fma2(wmA, mA, sq0);
                    { float a_, b_, c_, d_; upk2(a_, b_, wmA); upk2(c_, d_, mA);
                      tp0 = fmaf(a_, d_, tp0); }
                    u64 mB = rowB[k];
                    mu1 = fma2(wk, mB, mu1);
                    u64 wmB = mul2(wk, mB);
                    sq1 = fma2(wmB, mB, sq1);
                    { float a_, b_, c_, d_; upk2(a_, b_, wmB); upk2(c_, d_, mB);
                      tp1 = fmaf(a_, d_, tp1); }
                }
            }
            {
                const int u0 = (2 * j) % 11;
                rmu[u0] = mu0; rsq[u0] = sq0; rtp[u0] = tp0;
                if (i0 >= 10 && i0 < NLOADS) {
                    u64 cmu = 0ull, csq = 0ull; float ctp = 0.f;
                    #pragma unroll
                    for (int s = 0; s < 11; ++s) {
                        int d = (s - u0 + 10) % 11;
                        u64 wd = w2[d < 6 ? d : 10 - d];
                        cmu = fma2(wd, rmu[s], cmu);
                        csq = fma2(wd, rsq[s], csq);
                        ctp = fmaf(w[d], rtp[s], ctp);
                    }
                    float m1, m2, ett, epp;
                    upk2(m1, m2, cmu); upk2(ett, epp, csq);
                    float m1s = m1 * m1, m2s = m2 * m2, m12 = m1 * m2;
                    float v1 = fmaxf(ett - m1s, SSIM_EPS);
                    float v2 = fmaxf(epp - m2s, SSIM_EPS);
                    float v12 = ctp - m12;
                    float root = sqrtf(v1 * v2);
                    float num = (2.0f * m12 + C1_) * (2.0f * root + C2_) * (v12 + C3_);
                    float den = (m1s + m2s + C1_) * (v1 + v2 + C2_) * (root + C3_);
                    acc += __fdividef(num, den);
                }
            }
            {
                const int u1 = (2 * j + 1) % 11;
                rmu[u1] = mu1; rsq[u1] = sq1; rtp[u1] = tp1;
                if (i1 >= 10 && i1 < NLOADS) {
                    u64 cmu = 0ull, csq = 0ull; float ctp = 0.f;
                    #pragma unroll
                    for (int s = 0; s < 11; ++s) {
                        int d = (s - u1 + 10) % 11;
                        u64 wd = w2[d < 6 ? d : 10 - d];
                        cmu = fma2(wd, rmu[s], cmu);
                        csq = fma2(wd, rsq[s], csq);
                        ctp = fmaf(w[d], rtp[s], ctp);
                    }
                    float m1, m2, ett, epp;
                    upk2(m1, m2, cmu); upk2(ett, epp, csq);
                    float m1s = m1 * m1, m2s = m2 * m2, m12 = m1 * m2;
                    float v1 = fmaxf(ett - m1s, SSIM_EPS);
                    float v2 = fmaxf(epp - m2s, SSIM_EPS);
                    float v12 = ctp - m12;
                    float root = sqrtf(v1 * v2);
                    float num = (2.0f * m12 + C1_) * (2.0f * root + C2_) * (v12 + C3_);
                    float den = (m1s + m2s + C1_) * (v1 + v2 + C2_) * (root + C3_);
                    acc += __fdividef(num, den);
                }
            }
        }
    }
    #undef LOADROW

    // block reduce (4 warps) + single atomic
    #pragma unroll
    for (int o = 16; o; o >>= 1) acc += __shfl_xor_sync(~0u, acc, o);
    __shared__ float red[4];
    if ((tid & 31) == 0) red[tid >> 5] = acc;
    __syncthreads();
    __shared__ int amLast;
    if (tid == 0) {
        float t = red[0] + red[1] + red[2] + red[3];
        atomicAdd(&g_ssim[b], t);
        __threadfence();
        amLast = (atomicAdd(&g_cnt2, 1u) == GRID2 - 1);
    }
    __syncthreads();
    if (!amLast) return;

    // ---- fused final loss (last block) ----
    if (tid < 32) {
        float v = 0.f, s = 0.f;
        if (tid < NB) {
            v = g_valid[tid];
            s = (1.0f - g_ssim[tid] * (1.0f / (float)SAMPLE_ELEMS)) * v;
        }
        #pragma unroll
        for (int o = 16; o; o >>= 1) {
            s += __shfl_xor_sync(~0u, s, o);
            v += __shfl_xor_sync(~0u, v, o);
        }
        if (tid == 0) {
            float loss = s / fmaxf(v, 1.0f);
            for (int i = 0; i < out_size; ++i) out[i] = loss;
            g_cnt2 = 0;   // reset for next graph replay
        }
    }
}

extern "C" void kernel_launch(void* const* d_in, const int* in_sizes, int n_in,
                              void* d_out, int out_size) {
    const float* pred = (const float*)d_in[0];
    const float* tgt  = (const float*)d_in[1];
    float* out = (float*)d_out;

    reduce_kernel<<<GRID1, 256>>>(pred, tgt);
    conv_kernel<<<GRID2, BW>>>(pred, tgt, out, out_size);
}

// round 12
// speedup vs baseline: 1.7494x; 1.7494x over previous
#include <cuda_runtime.h>

#define HH 256
#define WW 256
#define NT 16
#define NB 8
#define NIMG (NB*NT)
#define HW (HH*WW)
#define SAMPLE_ELEMS (NT*HW)          // 1048576
#define WIN 11
#define PADW 5
#define SPLIT 2
#define SEG (HH/SPLIT)                // 128
#define NLOADS (SEG + 10)             // 138 rows per segment
#define BW 128                        // columns per block (4 warps x 32)
#define SW 32                         // columns per warp strip
#define RED_BLKS 64
#define GRID1 (NB*RED_BLKS)           // 512
#define GRID2 (NIMG*SPLIT*2)          // 512
#define SSIM_EPS 1e-6f
#define C1_ (1.0e-4f)
#define C2_ (9.0e-4f)
#define C3_ (4.5e-4f)

// canonical 11-tap sigma=1.5 gaussian
#define GW0 0.0010283799f
#define GW1 0.0075987583f
#define GW2 0.0360007723f
#define GW3 0.1093606947f
#define GW4 0.2130055329f
#define GW5 0.2660117190f

typedef unsigned long long u64;

// scratch (no allocations allowed)
__device__ float g_partial[5 * GRID1];   // stat-major: pmn,pmx,tmn,tmx,tsum
__device__ float g_params[NB * 4];       // mnt, invt, mnp, invp
__device__ float g_valid[NB];
__device__ float g_ssim[NB];
__device__ unsigned int g_cnt1;
__device__ unsigned int g_cnt2;

// ---- packed f32x2 helpers -------------------------------------------------
__device__ __forceinline__ u64 pk2(float x, float y) {
    u64 r; asm("mov.b64 %0,{%1,%2};" : "=l"(r) : "f"(x), "f"(y)); return r;
}
__device__ __forceinline__ void upk2(float& x, float& y, u64 v) {
    asm("mov.b64 {%0,%1},%2;" : "=f"(x), "=f"(y) : "l"(v));
}
__device__ __forceinline__ u64 fma2(u64 a, u64 b, u64 c) {
    u64 d; asm("fma.rn.f32x2 %0,%1,%2,%3;" : "=l"(d) : "l"(a), "l"(b), "l"(c)); return d;
}
__device__ __forceinline__ u64 mul2(u64 a, u64 b) {
    u64 d; asm("mul.rn.f32x2 %0,%1,%2;" : "=l"(d) : "l"(a), "l"(b)); return d;
}

// ---------------------------------------------------------------------------
// Kernel 1: per-sample min/max of pred & tgt, sum of tgt (64 blocks/sample),
//           fused finalize in the last-arriving block.
// ---------------------------------------------------------------------------
__global__ __launch_bounds__(256) void reduce_kernel(const float* __restrict__ pred,
                                                     const float* __restrict__ tgt) {
    int b   = blockIdx.x >> 6;
    int blk = blockIdx.x & 63;
    int tid = threadIdx.x;

    const float4* p4 = (const float4*)(pred + (size_t)b * SAMPLE_ELEMS + (size_t)blk * 16384);
    const float4* t4 = (const float4*)(tgt  + (size_t)b * SAMPLE_ELEMS + (size_t)blk * 16384);

    float pmn = 1e30f, pmx = -1e30f, tmn = 1e30f, tmx = -1e30f, ts = 0.f;
    #pragma unroll 4
    for (int i = tid; i < 4096; i += 256) {
        float4 a = p4[i];
        pmn = fminf(pmn, fminf(fminf(a.x, a.y), fminf(a.z, a.w)));
        pmx = fmaxf(pmx, fmaxf(fmaxf(a.x, a.y), fmaxf(a.z, a.w)));
        float4 c = t4[i];
        tmn = fminf(tmn, fminf(fminf(c.x, c.y), fminf(c.z, c.w)));
        tmx = fmaxf(tmx, fmaxf(fmaxf(c.x, c.y), fmaxf(c.z, c.w)));
        ts += (c.x + c.y) + (c.z + c.w);
    }
    #pragma unroll
    for (int o = 16; o; o >>= 1) {
        pmn = fminf(pmn, __shfl_xor_sync(~0u, pmn, o));
        pmx = fmaxf(pmx, __shfl_xor_sync(~0u, pmx, o));
        tmn = fminf(tmn, __shfl_xor_sync(~0u, tmn, o));
        tmx = fmaxf(tmx, __shfl_xor_sync(~0u, tmx, o));
        ts += __shfl_xor_sync(~0u, ts, o);
    }
    __shared__ float sm[8 * 5];
    int wid = tid >> 5;
    if ((tid & 31) == 0) {
        sm[wid * 5 + 0] = pmn; sm[wid * 5 + 1] = pmx;
        sm[wid * 5 + 2] = tmn; sm[wid * 5 + 3] = tmx;
        sm[wid * 5 + 4] = ts;
    }
    __syncthreads();
    if (tid == 0) {
        float a0 = sm[0], a1 = sm[1], a2 = sm[2], a3 = sm[3], a4 = sm[4];
        #pragma unroll
        for (int w = 1; w < 8; ++w) {
            a0 = fminf(a0, sm[w * 5 + 0]);
            a1 = fmaxf(a1, sm[w * 5 + 1]);
            a2 = fminf(a2, sm[w * 5 + 2]);
            a3 = fmaxf(a3, sm[w * 5 + 3]);
            a4 += sm[w * 5 + 4];
        }
        int base = b * RED_BLKS + blk;
        g_partial[0 * GRID1 + base] = a0;
        g_partial[1 * GRID1 + base] = a1;
        g_partial[2 * GRID1 + base] = a2;
        g_partial[3 * GRID1 + base] = a3;
        g_partial[4 * GRID1 + base] = a4;
        __threadfence();
    }
    __syncthreads();

    __shared__ int amLast;
    if (tid == 0) amLast = (atomicAdd(&g_cnt1, 1u) == GRID1 - 1);
    __syncthreads();
    if (!amLast) return;

    int wb  = tid >> 5;   // warp wb -> sample wb
    int lid = tid & 31;
    {
        int i0 = wb * RED_BLKS + lid;
        int i1 = i0 + 32;
        float a = fminf(g_partial[0 * GRID1 + i0], g_partial[0 * GRID1 + i1]);
        float c = fmaxf(g_partial[1 * GRID1 + i0], g_partial[1 * GRID1 + i1]);
        float d = fminf(g_partial[2 * GRID1 + i0], g_partial[2 * GRID1 + i1]);
        float e = fmaxf(g_partial[3 * GRID1 + i0], g_partial[3 * GRID1 + i1]);
        float s =       g_partial[4 * GRID1 + i0] + g_partial[4 * GRID1 + i1];
        #pragma unroll
        for (int o = 16; o; o >>= 1) {
            a = fminf(a, __shfl_xor_sync(~0u, a, o));
            c = fmaxf(c, __shfl_xor_sync(~0u, c, o));
            d = fminf(d, __shfl_xor_sync(~0u, d, o));
            e = fmaxf(e, __shfl_xor_sync(~0u, e, o));
            s += __shfl_xor_sync(~0u, s, o);
        }
        if (lid == 0) {
            float invp = 1.0f / fmaxf(c - a, SSIM_EPS);
            float invt = 1.0f / fmaxf(e - d, SSIM_EPS);
            g_params[wb * 4 + 0] = d;
            g_params[wb * 4 + 1] = invt;
            g_params[wb * 4 + 2] = a;
            g_params[wb * 4 + 3] = invp;
            g_valid[wb] = (s != 0.0f) ? 1.0f : 0.0f;
            g_ssim[wb]  = 0.0f;
        }
    }
    if (tid == 0) g_cnt1 = 0;   // reset for next graph replay
}

// ---------------------------------------------------------------------------
// Kernel 2: fused normalize + separable conv + SSIM, field-packed f32x2.
// WARP-AUTONOMOUS: each warp owns a 32-col output strip with its own
// 42-entry halo row buffer; __syncwarp only, no block barriers.
// Single row per iter, 2-slot rotating buffer, prefetch 1 row ahead.
// Last block computes the final scalar loss.
// ---------------------------------------------------------------------------
__global__ __launch_bounds__(BW, 4) void conv_kernel(const float* __restrict__ pred,
                                                     const float* __restrict__ tgt,
                                                     float* __restrict__ out, int out_size) {
    const float w[WIN] = {GW0, GW1, GW2, GW3, GW4, GW5, GW4, GW3, GW2, GW1, GW0};

    int blk  = blockIdx.x;
    int half = blk & 1;               // column half (0 -> cols 0..127, 1 -> 128..255)
    int seg  = (blk >> 1) & 1;        // row segment
    int n    = blk >> 2;              // frame
    int b    = n >> 4;
    int tid  = threadIdx.x;
    int wrp  = tid >> 5;
    int lane = tid & 31;
    int c0   = half * BW + wrp * SW;  // warp's strip start column

    float mnt  = g_params[b * 4 + 0];
    float invt = g_params[b * 4 + 1];
    float mnp  = g_params[b * 4 + 2];
    float invp = g_params[b * 4 + 3];
    float ctc = -mnt * invt;          // tn = fma(t, invt, ctc)
    float cpc = -mnp * invp;

    // 6 distinct packed weights (symmetric kernel)
    u64 w2[6];
    w2[0] = pk2(GW0, GW0); w2[1] = pk2(GW1, GW1); w2[2] = pk2(GW2, GW2);
    w2[3] = pk2(GW3, GW3); w2[4] = pk2(GW4, GW4); w2[5] = pk2(GW5, GW5);

    // per-warp rotating row buffers: [warp][slot][pos], pos 0..41 covers
    // global columns [c0-5, c0+36]. 48 entries for alignment.
    __shared__ u64 sb[4][2][48];

    int r0 = seg * SEG;
    const float* tb = tgt  + (size_t)n * HW;
    const float* pb = pred + (size_t)n * HW;

    int gcol  = c0 - PADW + lane;           // pos lane
    int gcol2 = gcol + SW;                  // pos lane+32 (lane<10)
    bool inc  = (gcol >= 0) && (gcol < WW);
    bool inc2 = (lane < 10) && (gcol2 < WW);

    u64 rmu[WIN], rsq[WIN];
    float rtp[WIN];
    float acc = 0.f;

    #define LOADROW(I, X0, X1) do {                                              \
        X0 = 0ull; X1 = 0ull;                                                    \
        int y_ = r0 - PADW + (I);                                                \
        if ((I) < NLOADS && y_ >= 0 && y_ < HH) {                                \
            if (inc)  { int id_ = y_ * WW + gcol;                                \
                X0 = pk2(fmaf(tb[id_], invt, ctc), fmaf(pb[id_], invp, cpc)); }  \
            if (inc2) { int id_ = y_ * WW + gcol2;                               \
                X1 = pk2(fmaf(tb[id_], invt, ctc), fmaf(pb[id_], invp, cpc)); }  \
        }                                                                        \
    } while (0)

    u64 cur0, cur1;
    LOADROW(0, cur0, cur1);

    #pragma unroll 1
    for (int base = 0; base < 143; base += 11) {
        #pragma unroll
        for (int u = 0; u < 11; ++u) {
            int i = base + u;                 // row index
            bool live = (i < NLOADS);
            int slot = i & 1;

            sb[wrp][slot][lane] = cur0;
            if (lane < 10) sb[wrp][slot][SW + lane] = cur1;
            __syncwarp();

            // prefetch row i+1 (full iteration of latency cover)
            LOADROW(i + 1, cur0, cur1);

            // horizontal conv, field-packed: mu={Σwt,Σwp}, sq={Σwt²,Σwp²}, tp=Σwtp
            u64 mu = 0ull, sq = 0ull;
            float tp = 0.f;
            {
                const u64* row = &sb[wrp][slot][lane];
                #pragma unroll
                for (int k = 0; k < WIN; ++k) {
                    u64 m  = row[k];            // LDS.64 {t,p}
                    u64 wk = w2[k < 6 ? k : 10 - k];
                    mu = fma2(wk, m, mu);
                    u64 wm = mul2(wk, m);       // {w t, w p}
                    sq = fma2(wm, m, sq);
                    float a_, b_, c_, d_;
                    upk2(a_, b_, wm); upk2(c_, d_, m);     // free
                    tp = fmaf(a_, d_, tp);
                }
            }
            rmu[u] = mu; rsq[u] = sq; rtp[u] = tp;

            if (i >= 10 && live) {
                // vertical conv (output row oy = r0 + i - 10)
                u64 cmu = 0ull, csq = 0ull;
                float ctp = 0.f;
                #pragma unroll
                for (int s = 0; s < 11; ++s) {
                    int d = (s - u + 10) % 11;       // compile-time per (u,s)
                    u64 wd = w2[d < 6 ? d : 10 - d];
                    cmu = fma2(wd, rmu[s], cmu);
                    csq = fma2(wd, rsq[s], csq);
                    ctp = fmaf(w[d], rtp[s], ctp);
                }
                float m1, m2, ett, epp;
                upk2(m1, m2, cmu);
                upk2(ett, epp, csq);
                float m1s = m1 * m1, m2s = m2 * m2, m12 = m1 * m2;
                float v1  = fmaxf(ett - m1s, SSIM_EPS);
                float v2  = fmaxf(epp - m2s, SSIM_EPS);
                float v12 = ctp - m12;
                float root = sqrtf(v1 * v2);
                float num = (2.0f * m12 + C1_) * (2.0f * root + C2_) * (v12 + C3_);
                float den = (m1s + m2s + C1_) * (v1 + v2 + C2_) * (root + C3_);
                acc += __fdividef(num, den);
            }
        }
    }
    #undef LOADROW

    // block reduce (4 warps) + single atomic
    #pragma unroll
    for (int o = 16; o; o >>= 1) acc += __shfl_xor_sync(~0u, acc, o);
    __shared__ float red[4];
    if (lane == 0) red[wrp] = acc;
    __syncthreads();
    __shared__ int amLast;
    if (tid == 0) {
        float t = red[0] + red[1] + red[2] + red[3];
        atomicAdd(&g_ssim[b], t);
        __threadfence();
        amLast = (atomicAdd(&g_cnt2, 1u) == GRID2 - 1);
    }
    __syncthreads();
    if (!amLast) return;

    // ---- fused final loss (last block) ----
    if (tid < 32) {
        float v = 0.f, s = 0.f;
        if (tid < NB) {
            v = g_valid[tid];
            s = (1.0f - g_ssim[tid] * (1.0f / (float)SAMPLE_ELEMS)) * v;
        }
        #pragma unroll
        for (int o = 16; o; o >>= 1) {
            s += __shfl_xor_sync(~0u, s, o);
            v += __shfl_xor_sync(~0u, v, o);
        }
        if (tid == 0) {
            float loss = s / fmaxf(v, 1.0f);
            for (int i = 0; i < out_size; ++i) out[i] = loss;
            g_cnt2 = 0;   // reset for next graph replay
        }
    }
}

extern "C" void kernel_launch(void* const* d_in, const int* in_sizes, int n_in,
                              void* d_out, int out_size) {
    const float* pred = (const float*)d_in[0];
    const float* tgt  = (const float*)d_in[1];
    float* out = (float*)d_out;

    reduce_kernel<<<GRID1, 256>>>(pred, tgt);
    conv_kernel<<<GRID2, BW>>>(pred, tgt, out, out_size);
}